// round 1
// baseline (speedup 1.0000x reference)
#include <cuda_runtime.h>

#define HW     131072      // h*w = 256*512
#define C      128
#define LTOT   163840      // Q*M*M
#define KS     9
#define TL     16          // l-values per block in main kernel
#define XES    1168        // padded l-row stride in smem words (9*128 + 16; ==16 mod 32, ==0 mod 4)
#define PLANE  16384       // M*M
#define SMEM_MAIN ((TL*XES + 3*TL*KS + TL*KS) * 4)

// Scratch (allocation-free rule: device globals)
__device__ __align__(16) float  g_xt[(size_t)HW * C];   // transposed x: [hw][c]
__device__ double g_sum[C];
__device__ double g_sumsq[C];
__device__ float  g_a[C];
__device__ float  g_b[C];

// ---------------------------------------------------------------------------
__global__ void zero_stats_k() {
    int t = threadIdx.x;
    if (t < C) { g_sum[t] = 0.0; g_sumsq[t] = 0.0; }
}

// x [C][HW] -> g_xt [HW][C]
__global__ void transpose_k(const float* __restrict__ x) {
    __shared__ float tile[32][33];
    int hw0 = blockIdx.x * 32;
    int c0  = blockIdx.y * 32;
    int tx = threadIdx.x, ty = threadIdx.y;
#pragma unroll
    for (int i = 0; i < 32; i += 8)
        tile[ty + i][tx] = x[(size_t)(c0 + ty + i) * HW + hw0 + tx];
    __syncthreads();
#pragma unroll
    for (int i = 0; i < 32; i += 8)
        g_xt[(size_t)(hw0 + ty + i) * C + c0 + tx] = tile[tx][ty + i];
}

// ---------------------------------------------------------------------------
// One block = 16 consecutive l values. 256 threads (8 warps).
// Phase 1: gather 144 rows of 128 channels into smem; fused mean/max per row.
// Phase 2: 9-way attention matvec + sigmoid per (l,o).
// Phase 3: depthwise dot over k, coalesced float4 writes, BN stat atomics.
__global__ void __launch_bounds__(256) main_k(
    const int*   __restrict__ codes,
    const float* __restrict__ att_w,   // [KS][2][KS]
    const float* __restrict__ att_b,   // [KS]
    const float* __restrict__ depth_w, // [C][KS]
    const float* __restrict__ depth_b, // [C]
    float*       __restrict__ dout)
{
    extern __shared__ float sm[];
    float* xe   = sm;                       // [TL][XES]  (xe[l][k*128 + c])
    float* savg = xe + TL * XES;            // [TL][KS]
    float* smax = savg + TL * KS;           // [TL][KS]
    float* attp = smax + TL * KS;           // [TL][KS]   (1 + sigmoid(att))
    int*   sidx = (int*)(attp + TL * KS);   // [TL*KS]

    const int t    = threadIdx.x;
    const int lane = t & 31;
    const int wid  = t >> 5;
    const int l0   = blockIdx.x * TL;

    if (t < TL * KS) sidx[t] = codes[l0 * KS + t];
    __syncthreads();

    // ---- gather + fused per-row mean/max ----
    for (int r = wid; r < TL * KS; r += 8) {
        int j = sidx[r];
        float4 v = *(const float4*)(g_xt + (size_t)j * C + lane * 4);
        *(float4*)(xe + (r / KS) * XES + (r % KS) * C + lane * 4) = v;
        float s = (v.x + v.y) + (v.z + v.w);
        float m = fmaxf(fmaxf(v.x, v.y), fmaxf(v.z, v.w));
#pragma unroll
        for (int off = 16; off > 0; off >>= 1) {
            s += __shfl_xor_sync(0xffffffffu, s, off);
            m  = fmaxf(m, __shfl_xor_sync(0xffffffffu, m, off));
        }
        if (lane == 0) { savg[r] = s * (1.0f / C); smax[r] = m; }
    }
    __syncthreads();

    // ---- attention matvec + sigmoid ----
    if (t < TL * KS) {
        int l = t / KS, o = t % KS;
        float a = att_b[o];
#pragma unroll
        for (int k = 0; k < KS; k++)
            a += savg[l * KS + k] * att_w[(o * 2    ) * KS + k]
               + smax[l * KS + k] * att_w[(o * 2 + 1) * KS + k];
        attp[t] = 1.0f + 1.0f / (1.0f + expf(-a));
    }
    __syncthreads();

    // ---- depthwise output + BN stats ----
    const int c    = t >> 1;      // 0..127
    const int half = t & 1;       // l-halves 0..7 / 8..15

    float wk[KS];
#pragma unroll
    for (int k = 0; k < KS; k++) wk[k] = depth_w[c * KS + k];
    const float dbias = depth_b[c];

    float vals[8];
    float s1 = 0.f, s2 = 0.f;
#pragma unroll
    for (int i = 0; i < 8; i++) {
        const int ll = half * 8 + i;
        const float* xr = xe + ll * XES + c;
        const float* ar = attp + ll * KS;
        float v = dbias;
#pragma unroll
        for (int k = 0; k < KS; k++)
            v += xr[k * C] * ar[k] * wk[k];
        vals[i] = v;
        s1 += v;
        s2 += v * v;
    }

    const int q  = l0 >> 14;                       // l0 / PLANE
    const int rr = (l0 & (PLANE - 1)) + half * 8;
    float* ob = dout + (size_t)q * (C * PLANE) + (size_t)c * PLANE + rr;
    *(float4*)(ob)     = make_float4(vals[0], vals[1], vals[2], vals[3]);
    *(float4*)(ob + 4) = make_float4(vals[4], vals[5], vals[6], vals[7]);

    s1 += __shfl_xor_sync(0xffffffffu, s1, 1);
    s2 += __shfl_xor_sync(0xffffffffu, s2, 1);
    if (half == 0) {
        atomicAdd(&g_sum[c],   (double)s1);
        atomicAdd(&g_sumsq[c], (double)s2);
    }
}

// ---------------------------------------------------------------------------
__global__ void bn_params_k(const float* __restrict__ gamma,
                            const float* __restrict__ beta) {
    int c = threadIdx.x;
    double mean = g_sum[c]   * (1.0 / LTOT);
    double var  = g_sumsq[c] * (1.0 / LTOT) - mean * mean;
    float inv = rsqrtf((float)var + 1e-5f);
    float a = gamma[c] * inv;
    g_a[c] = a;
    g_b[c] = beta[c] - (float)mean * a;
}

__global__ void finalize_k(float* __restrict__ out) {
    int i = blockIdx.x * blockDim.x + threadIdx.x;    // float4 index, 5242880 total
    int c = (i >> 12) & 127;                          // (i*4) / PLANE % C
    float a = g_a[c], b = g_b[c];
    float4 v = ((const float4*)out)[i];
    float4 r;
    r.x = a * v.x + b;  r.x = r.x / (1.f + expf(-r.x));
    r.y = a * v.y + b;  r.y = r.y / (1.f + expf(-r.y));
    r.z = a * v.z + b;  r.z = r.z / (1.f + expf(-r.z));
    r.w = a * v.w + b;  r.w = r.w / (1.f + expf(-r.w));
    ((float4*)out)[i] = r;
}

// ---------------------------------------------------------------------------
extern "C" void kernel_launch(void* const* d_in, const int* in_sizes, int n_in,
                              void* d_out, int out_size) {
    const float* x       = (const float*)d_in[0];
    const int*   codes   = (const int*)  d_in[1];
    const float* att_w   = (const float*)d_in[2];
    const float* att_b   = (const float*)d_in[3];
    const float* depth_w = (const float*)d_in[4];
    const float* depth_b = (const float*)d_in[5];
    const float* gamma   = (const float*)d_in[6];
    const float* beta    = (const float*)d_in[7];
    float* out = (float*)d_out;

    cudaFuncSetAttribute(main_k, cudaFuncAttributeMaxDynamicSharedMemorySize,
                         SMEM_MAIN);

    zero_stats_k<<<1, 128>>>();
    transpose_k<<<dim3(HW / 32, C / 32), dim3(32, 8)>>>(x);
    main_k<<<LTOT / TL, 256, SMEM_MAIN>>>(codes, att_w, att_b,
                                          depth_w, depth_b, out);
    bn_params_k<<<1, 128>>>(gamma, beta);
    finalize_k<<<(LTOT * C / 4) / 256, 256>>>(out);
}

// round 2
// speedup vs baseline: 1.5518x; 1.5518x over previous
#include <cuda_runtime.h>

#define HW     131072      // h*w = 256*512
#define C      128
#define LTOT   163840      // Q*M*M
#define KS     9
#define TL     8           // l-values per block in main kernel
#define NROW   (TL*KS)     // 72 gathered rows per block
#define XES    1156        // padded l-row stride in smem words (9*128+4; ==4 mod 8)
#define PLANE  16384       // M*M
#define NB     32          // BN stat buckets
#define SMEM_MAIN ((TL*XES + 4*NROW) * 4)

// Scratch (allocation-free rule: device globals)
__device__ __align__(16) float  g_xt[(size_t)HW * C];   // transposed x: [hw][c]
__device__ double g_sum[C * NB];
__device__ double g_sumsq[C * NB];
__device__ float  g_a[C];
__device__ float  g_b[C];

// ---------------------------------------------------------------------------
__global__ void zero_stats_k() {
    for (int i = threadIdx.x; i < C * NB; i += blockDim.x) {
        g_sum[i] = 0.0; g_sumsq[i] = 0.0;
    }
}

// x [C][HW] -> g_xt [HW][C]
__global__ void transpose_k(const float* __restrict__ x) {
    __shared__ float tile[32][33];
    int hw0 = blockIdx.x * 32;
    int c0  = blockIdx.y * 32;
    int tx = threadIdx.x, ty = threadIdx.y;
#pragma unroll
    for (int i = 0; i < 32; i += 8)
        tile[ty + i][tx] = x[(size_t)(c0 + ty + i) * HW + hw0 + tx];
    __syncthreads();
#pragma unroll
    for (int i = 0; i < 32; i += 8)
        g_xt[(size_t)(hw0 + ty + i) * C + c0 + tx] = tile[tx][ty + i];
}

// ---------------------------------------------------------------------------
// One block = 8 consecutive l values. 256 threads (8 warps).
// Phase 1a: batched gather (9 independent LDG.128 per warp -> regs -> smem).
// Phase 1b: per-row mean/max via shfl on register values.
// Phase 2:  9-way attention matvec + sigmoid per (l,o).
// Phase 3:  depthwise dot over k, coalesced float4 writes, bucketed BN atomics.
__global__ void __launch_bounds__(256) main_k(
    const int*   __restrict__ codes,
    const float* __restrict__ att_w,   // [KS][2][KS]
    const float* __restrict__ att_b,   // [KS]
    const float* __restrict__ depth_w, // [C][KS]
    const float* __restrict__ depth_b, // [C]
    float*       __restrict__ dout)
{
    extern __shared__ float sm[];
    float* xe   = sm;                       // [TL][XES]  (xe[l][k*128 + c])
    float* savg = xe + TL * XES;            // [NROW]
    float* smax = savg + NROW;              // [NROW]
    float* attp = smax + NROW;              // [NROW]   (1 + sigmoid(att))
    int*   sidx = (int*)(attp + NROW);      // [NROW]

    const int t    = threadIdx.x;
    const int lane = t & 31;
    const int wid  = t >> 5;
    const int l0   = blockIdx.x * TL;

    if (t < NROW) sidx[t] = codes[l0 * KS + t];
    __syncthreads();

    // ---- phase 1a: batched gather (all loads independent -> full MLP) ----
    float4 v[9];
#pragma unroll
    for (int ii = 0; ii < 9; ii++) {
        const int r = wid + ii * 8;
        const int j = sidx[r];
        v[ii] = *(const float4*)(g_xt + (size_t)j * C + lane * 4);
    }
#pragma unroll
    for (int ii = 0; ii < 9; ii++) {
        const int r = wid + ii * 8;
        *(float4*)(xe + (r / KS) * XES + (r % KS) * C + lane * 4) = v[ii];
    }

    // ---- phase 1b: per-row mean/max from registers ----
#pragma unroll
    for (int ii = 0; ii < 9; ii++) {
        const int r = wid + ii * 8;
        float s = (v[ii].x + v[ii].y) + (v[ii].z + v[ii].w);
        float m = fmaxf(fmaxf(v[ii].x, v[ii].y), fmaxf(v[ii].z, v[ii].w));
#pragma unroll
        for (int off = 16; off > 0; off >>= 1) {
            s += __shfl_xor_sync(0xffffffffu, s, off);
            m  = fmaxf(m, __shfl_xor_sync(0xffffffffu, m, off));
        }
        if (lane == 0) { savg[r] = s * (1.0f / C); smax[r] = m; }
    }
    __syncthreads();

    // ---- phase 2: attention matvec + sigmoid ----
    if (t < NROW) {
        int l = t / KS, o = t % KS;
        float a = att_b[o];
#pragma unroll
        for (int k = 0; k < KS; k++)
            a += savg[l * KS + k] * att_w[(o * 2    ) * KS + k]
               + smax[l * KS + k] * att_w[(o * 2 + 1) * KS + k];
        attp[t] = 1.0f + 1.0f / (1.0f + __expf(-a));
    }
    __syncthreads();

    // ---- phase 3: depthwise output + BN stats ----
    const int c    = t >> 1;      // 0..127
    const int half = t & 1;       // l-halves [0..3] / [4..7]

    float wk[KS];
#pragma unroll
    for (int k = 0; k < KS; k++) wk[k] = depth_w[c * KS + k];
    const float dbias = depth_b[c];

    float vals[4];
    float s1 = 0.f, s2 = 0.f;
#pragma unroll
    for (int i = 0; i < 4; i++) {
        const int ll = half * 4 + i;
        const float* xr = xe + ll * XES + c;
        const float* ar = attp + ll * KS;
        float o = dbias;
#pragma unroll
        for (int k = 0; k < KS; k++)
            o += xr[k * C] * ar[k] * wk[k];
        vals[i] = o;
        s1 += o;
        s2 += o * o;
    }

    const int q  = l0 >> 14;                       // l0 / PLANE
    const int rr = (l0 & (PLANE - 1)) + half * 4;
    float* ob = dout + (size_t)q * (C * PLANE) + (size_t)c * PLANE + rr;
    *(float4*)ob = make_float4(vals[0], vals[1], vals[2], vals[3]);

    s1 += __shfl_xor_sync(0xffffffffu, s1, 1);
    s2 += __shfl_xor_sync(0xffffffffu, s2, 1);
    if (half == 0) {
        const int bkt = blockIdx.x & (NB - 1);
        atomicAdd(&g_sum[c * NB + bkt],   (double)s1);
        atomicAdd(&g_sumsq[c * NB + bkt], (double)s2);
    }
}

// ---------------------------------------------------------------------------
__global__ void bn_params_k(const float* __restrict__ gamma,
                            const float* __restrict__ beta) {
    int c = threadIdx.x;
    double s1 = 0.0, s2 = 0.0;
#pragma unroll
    for (int b = 0; b < NB; b++) { s1 += g_sum[c * NB + b]; s2 += g_sumsq[c * NB + b]; }
    double mean = s1 * (1.0 / LTOT);
    double var  = s2 * (1.0 / LTOT) - mean * mean;
    float inv = rsqrtf((float)var + 1e-5f);
    float a = gamma[c] * inv;
    g_a[c] = a;
    g_b[c] = beta[c] - (float)mean * a;
}

__global__ void finalize_k(float* __restrict__ out) {
    int i = blockIdx.x * blockDim.x + threadIdx.x;    // float4 index, 5242880 total
    int c = (i >> 12) & 127;                          // (i*4) / PLANE % C
    float a = g_a[c], b = g_b[c];
    float4 v = ((const float4*)out)[i];
    float4 r;
    r.x = a * v.x + b;  r.x = r.x / (1.f + __expf(-r.x));
    r.y = a * v.y + b;  r.y = r.y / (1.f + __expf(-r.y));
    r.z = a * v.z + b;  r.z = r.z / (1.f + __expf(-r.z));
    r.w = a * v.w + b;  r.w = r.w / (1.f + __expf(-r.w));
    ((float4*)out)[i] = r;
}

// ---------------------------------------------------------------------------
extern "C" void kernel_launch(void* const* d_in, const int* in_sizes, int n_in,
                              void* d_out, int out_size) {
    const float* x       = (const float*)d_in[0];
    const int*   codes   = (const int*)  d_in[1];
    const float* att_w   = (const float*)d_in[2];
    const float* att_b   = (const float*)d_in[3];
    const float* depth_w = (const float*)d_in[4];
    const float* depth_b = (const float*)d_in[5];
    const float* gamma   = (const float*)d_in[6];
    const float* beta    = (const float*)d_in[7];
    float* out = (float*)d_out;

    cudaFuncSetAttribute(main_k, cudaFuncAttributeMaxDynamicSharedMemorySize,
                         SMEM_MAIN);

    zero_stats_k<<<1, 256>>>();
    transpose_k<<<dim3(HW / 32, C / 32), dim3(32, 8)>>>(x);
    main_k<<<LTOT / TL, 256, SMEM_MAIN>>>(codes, att_w, att_b,
                                          depth_w, depth_b, out);
    bn_params_k<<<1, 128>>>(gamma, beta);
    finalize_k<<<(LTOT * C / 4) / 256, 256>>>(out);
}

// round 3
// speedup vs baseline: 1.6915x; 1.0901x over previous
#include <cuda_runtime.h>

#define HW     131072      // h*w = 256*512
#define C      128
#define LTOT   163840      // Q*M*M
#define KS     9
#define TLB    32          // l-values per block
#define WPB    8           // warps per block
#define ROUNDS (TLB/WPB)
#define OSTR   132         // staging stride (words) per l row
#define PLANE  16384       // M*M
#define NB     32          // BN stat buckets

// Scratch (allocation-free rule: device globals)
__device__ __align__(16) float  g_xt[(size_t)HW * C];   // transposed x: [hw][c]
__device__ double g_sum[C * NB];
__device__ double g_sumsq[C * NB];
__device__ float  g_a[C];
__device__ float  g_b[C];

// ---------------------------------------------------------------------------
// x [C][HW] -> g_xt [HW][C]; block (0,0) also zeroes the BN stat buckets.
__global__ void transpose_k(const float* __restrict__ x) {
    __shared__ float tile[32][33];
    int hw0 = blockIdx.x * 32;
    int c0  = blockIdx.y * 32;
    int tx = threadIdx.x, ty = threadIdx.y;
    if (blockIdx.x == 0 && blockIdx.y == 0) {
        int tid = ty * 32 + tx;
        for (int i = tid; i < C * NB; i += 256) { g_sum[i] = 0.0; g_sumsq[i] = 0.0; }
    }
#pragma unroll
    for (int i = 0; i < 32; i += 8)
        tile[ty + i][tx] = x[(size_t)(c0 + ty + i) * HW + hw0 + tx];
    __syncthreads();
#pragma unroll
    for (int i = 0; i < 32; i += 8)
        g_xt[(size_t)(hw0 + ty + i) * C + c0 + tx] = tile[tx][ty + i];
}

// ---------------------------------------------------------------------------
// One block = 32 l values; 8 warps, each warp does one l per round (4 rounds).
// Per warp-round: gather 9 rows (float4/lane, registers), butterfly mean/max,
// in-warp attention (lane o<9 computes one logit, shfl broadcast), depthwise
// accumulate in registers, STS.128 stage. Epilogue: coalesced float4 stores +
// bucketed BN stat atomics.
__global__ void __launch_bounds__(256, 2) main_k(
    const int*   __restrict__ codes,
    const float* __restrict__ att_w,   // [KS][2][KS]
    const float* __restrict__ att_b,   // [KS]
    const float* __restrict__ depth_w, // [C][KS]
    const float* __restrict__ depth_b, // [C]
    float*       __restrict__ dout)
{
    __shared__ float sm_out[TLB * OSTR];       // [l_local][c] staging
    __shared__ float sm_aw[KS * 2 * KS];       // att_w copy
    __shared__ float sm_ab[KS];

    const int t    = threadIdx.x;
    const int lane = t & 31;
    const int wid  = t >> 5;
    const int l0   = blockIdx.x * TLB;
    const int c0   = lane * 4;

    if (t < KS * 2 * KS) sm_aw[t] = att_w[t];
    if (t < KS)          sm_ab[t] = att_b[t];

    // persistent per-thread depthwise params (lane -> channels c0..c0+3)
    float w0[KS], w1[KS], w2[KS], w3[KS];
#pragma unroll
    for (int k = 0; k < KS; k++) {
        w0[k] = depth_w[(c0 + 0) * KS + k];
        w1[k] = depth_w[(c0 + 1) * KS + k];
        w2[k] = depth_w[(c0 + 2) * KS + k];
        w3[k] = depth_w[(c0 + 3) * KS + k];
    }
    const float4 db = *(const float4*)(depth_b + c0);
    __syncthreads();

#pragma unroll
    for (int r = 0; r < ROUNDS; r++) {
        const int ll = r * WPB + wid;          // local l
        const int l  = l0 + ll;

        int myidx = 0;
        if (lane < KS) myidx = codes[l * KS + lane];

        // gather: 9 independent LDG.128
        float4 v[KS];
#pragma unroll
        for (int k = 0; k < KS; k++) {
            int j = __shfl_sync(0xffffffffu, myidx, k);
            v[k] = *(const float4*)(g_xt + (size_t)j * C + c0);
        }

        // per-row mean/max, full butterfly -> all lanes hold results
        float sa[KS], sx[KS];
#pragma unroll
        for (int k = 0; k < KS; k++) {
            float s = (v[k].x + v[k].y) + (v[k].z + v[k].w);
            float m = fmaxf(fmaxf(v[k].x, v[k].y), fmaxf(v[k].z, v[k].w));
#pragma unroll
            for (int off = 16; off > 0; off >>= 1) {
                s += __shfl_xor_sync(0xffffffffu, s, off);
                m  = fmaxf(m, __shfl_xor_sync(0xffffffffu, m, off));
            }
            sa[k] = s * (1.0f / C);
            sx[k] = m;
        }

        // attention: lane o<9 computes logit o, broadcast 1+sigmoid
        float attp = 0.f;
        if (lane < KS) {
            float a = sm_ab[lane];
#pragma unroll
            for (int k = 0; k < KS; k++)
                a += sa[k] * sm_aw[(lane * 2    ) * KS + k]
                   + sx[k] * sm_aw[(lane * 2 + 1) * KS + k];
            attp = 1.0f + 1.0f / (1.0f + __expf(-a));
        }
        float ap[KS];
#pragma unroll
        for (int k = 0; k < KS; k++)
            ap[k] = __shfl_sync(0xffffffffu, attp, k);

        // depthwise accumulate in registers
        float4 acc = db;
#pragma unroll
        for (int k = 0; k < KS; k++) {
            acc.x = fmaf(v[k].x, ap[k] * w0[k], acc.x);
            acc.y = fmaf(v[k].y, ap[k] * w1[k], acc.y);
            acc.z = fmaf(v[k].z, ap[k] * w2[k], acc.z);
            acc.w = fmaf(v[k].w, ap[k] * w3[k], acc.w);
        }
        *(float4*)(sm_out + ll * OSTR + c0) = acc;
    }
    __syncthreads();

    // epilogue: coalesced stores + BN stats
    const int c    = t >> 1;
    const int half = t & 1;
    const int q    = l0 >> 14;                         // l0 / PLANE
    const int rr   = (l0 & (PLANE - 1)) + half * 16;
    float* ob = dout + (size_t)q * (C * PLANE) + (size_t)c * PLANE + rr;

    float s1 = 0.f, s2 = 0.f;
#pragma unroll
    for (int i = 0; i < 4; i++) {
        float4 o4;
        o4.x = sm_out[(half * 16 + i * 4 + 0) * OSTR + c];
        o4.y = sm_out[(half * 16 + i * 4 + 1) * OSTR + c];
        o4.z = sm_out[(half * 16 + i * 4 + 2) * OSTR + c];
        o4.w = sm_out[(half * 16 + i * 4 + 3) * OSTR + c];
        s1 += (o4.x + o4.y) + (o4.z + o4.w);
        s2 += o4.x * o4.x + o4.y * o4.y + o4.z * o4.z + o4.w * o4.w;
        ((float4*)ob)[i] = o4;
    }

    s1 += __shfl_xor_sync(0xffffffffu, s1, 1);
    s2 += __shfl_xor_sync(0xffffffffu, s2, 1);
    if (half == 0) {
        const int bkt = blockIdx.x & (NB - 1);
        atomicAdd(&g_sum[c * NB + bkt],   (double)s1);
        atomicAdd(&g_sumsq[c * NB + bkt], (double)s2);
    }
}

// ---------------------------------------------------------------------------
__global__ void bn_params_k(const float* __restrict__ gamma,
                            const float* __restrict__ beta) {
    int c = threadIdx.x;
    double s1 = 0.0, s2 = 0.0;
#pragma unroll
    for (int b = 0; b < NB; b++) { s1 += g_sum[c * NB + b]; s2 += g_sumsq[c * NB + b]; }
    double mean = s1 * (1.0 / LTOT);
    double var  = s2 * (1.0 / LTOT) - mean * mean;
    float inv = rsqrtf((float)var + 1e-5f);
    float a = gamma[c] * inv;
    g_a[c] = a;
    g_b[c] = beta[c] - (float)mean * a;
}

__global__ void finalize_k(float* __restrict__ out) {
    int i = blockIdx.x * blockDim.x + threadIdx.x;    // float4 index
    int c = (i >> 12) & 127;                          // (i*4) / PLANE % C
    float a = g_a[c], b = g_b[c];
    float4 v = ((const float4*)out)[i];
    float4 r;
    r.x = a * v.x + b;  r.x = r.x / (1.f + __expf(-r.x));
    r.y = a * v.y + b;  r.y = r.y / (1.f + __expf(-r.y));
    r.z = a * v.z + b;  r.z = r.z / (1.f + __expf(-r.z));
    r.w = a * v.w + b;  r.w = r.w / (1.f + __expf(-r.w));
    ((float4*)out)[i] = r;
}

// ---------------------------------------------------------------------------
extern "C" void kernel_launch(void* const* d_in, const int* in_sizes, int n_in,
                              void* d_out, int out_size) {
    const float* x       = (const float*)d_in[0];
    const int*   codes   = (const int*)  d_in[1];
    const float* att_w   = (const float*)d_in[2];
    const float* att_b   = (const float*)d_in[3];
    const float* depth_w = (const float*)d_in[4];
    const float* depth_b = (const float*)d_in[5];
    const float* gamma   = (const float*)d_in[6];
    const float* beta    = (const float*)d_in[7];
    float* out = (float*)d_out;

    transpose_k<<<dim3(HW / 32, C / 32), dim3(32, 8)>>>(x);
    main_k<<<LTOT / TLB, 256>>>(codes, att_w, att_b, depth_w, depth_b, out);
    bn_params_k<<<1, 128>>>(gamma, beta);
    finalize_k<<<(LTOT * C / 4) / 256, 256>>>(out);
}

// round 4
// speedup vs baseline: 1.8281x; 1.0807x over previous
#include <cuda_runtime.h>

#define HW     131072      // h*w = 256*512
#define C      128
#define LTOT   163840      // Q*M*M
#define KS     9
#define TLB    32          // l-values per block
#define WPB    8           // warps per block
#define ROUNDS (TLB/WPB)
#define OSTR   132         // staging stride (words) per l row
#define PLANE  16384       // M*M
#define NB     32          // BN stat buckets

// Scratch (allocation-free rule: device globals)
__device__ __align__(16) float  g_xt[(size_t)HW * C];   // transposed x: [hw][c]
__device__ __align__(8)  float2 g_stat[HW];             // per-position (mean, max) over c
__device__ double g_sum[C * NB];
__device__ double g_sumsq[C * NB];
__device__ float  g_a[C];
__device__ float  g_b[C];

// ---------------------------------------------------------------------------
// Per-position channel mean/max: column reduction over x [C][HW].
// Fully coalesced; also zeroes BN stat buckets (block 0).
__global__ void __launch_bounds__(256) rowstat_k(const float* __restrict__ x) {
    const int hw = blockIdx.x * 256 + threadIdx.x;
    if (blockIdx.x == 0) {
        for (int i = threadIdx.x; i < C * NB; i += 256) {
            g_sum[i] = 0.0; g_sumsq[i] = 0.0;
        }
    }
    float s = 0.f, m = -3.4e38f;
#pragma unroll 16
    for (int c = 0; c < C; c++) {
        float v = x[(size_t)c * HW + hw];
        s += v;
        m = fmaxf(m, v);
    }
    g_stat[hw] = make_float2(s * (1.0f / C), m);
}

// x [C][HW] -> g_xt [HW][C]
__global__ void transpose_k(const float* __restrict__ x) {
    __shared__ float tile[32][33];
    int hw0 = blockIdx.x * 32;
    int c0  = blockIdx.y * 32;
    int tx = threadIdx.x, ty = threadIdx.y;
#pragma unroll
    for (int i = 0; i < 32; i += 8)
        tile[ty + i][tx] = x[(size_t)(c0 + ty + i) * HW + hw0 + tx];
    __syncthreads();
#pragma unroll
    for (int i = 0; i < 32; i += 8)
        g_xt[(size_t)(hw0 + ty + i) * C + c0 + tx] = tile[tx][ty + i];
}

// ---------------------------------------------------------------------------
// One block = 32 l values; 8 warps, each warp does one l per round (4 rounds).
// Per warp-round: 9 independent LDG.128 gathers; per-position stats are
// PRECOMPUTED (no butterflies) -> lane k<9 loads stat[j_k], 18 bcast shfls,
// in-warp attention, depthwise accumulate in regs, STS.128 stage.
// Epilogue: coalesced float4 stores + bucketed BN stat atomics.
__global__ void __launch_bounds__(256, 2) main_k(
    const int*   __restrict__ codes,
    const float* __restrict__ att_w,   // [KS][2][KS]
    const float* __restrict__ att_b,   // [KS]
    const float* __restrict__ depth_w, // [C][KS]
    const float* __restrict__ depth_b, // [C]
    float*       __restrict__ dout)
{
    __shared__ float sm_out[TLB * OSTR];       // [l_local][c] staging
    __shared__ float sm_aw[KS * 2 * KS];       // att_w copy
    __shared__ float sm_ab[KS];
    __shared__ int   sidx[TLB * KS];           // 288 codes

    const int t    = threadIdx.x;
    const int lane = t & 31;
    const int wid  = t >> 5;
    const int l0   = blockIdx.x * TLB;
    const int c0   = lane * 4;

    if (t < KS * 2 * KS) sm_aw[t] = att_w[t];
    if (t < KS)          sm_ab[t] = att_b[t];
    for (int i = t; i < TLB * KS; i += 256) sidx[i] = codes[l0 * KS + i];

    // persistent per-thread depthwise params (lane -> channels c0..c0+3)
    float w0[KS], w1[KS], w2[KS], w3[KS];
#pragma unroll
    for (int k = 0; k < KS; k++) {
        w0[k] = depth_w[(c0 + 0) * KS + k];
        w1[k] = depth_w[(c0 + 1) * KS + k];
        w2[k] = depth_w[(c0 + 2) * KS + k];
        w3[k] = depth_w[(c0 + 3) * KS + k];
    }
    const float4 db = *(const float4*)(depth_b + c0);
    __syncthreads();

#pragma unroll
    for (int r = 0; r < ROUNDS; r++) {
        const int ll = r * WPB + wid;          // local l

        // gather: 9 independent LDG.128 (indices via LDS broadcast)
        float4 v[KS];
#pragma unroll
        for (int k = 0; k < KS; k++) {
            int j = sidx[ll * KS + k];
            v[k] = *(const float4*)(g_xt + (size_t)j * C + c0);
        }

        // precomputed per-position stats: lane k<9 loads its row's (avg,max)
        float sa_own = 0.f, sx_own = 0.f;
        if (lane < KS) {
            float2 st = g_stat[sidx[ll * KS + lane]];
            sa_own = st.x; sx_own = st.y;
        }
        float sa[KS], sx[KS];
#pragma unroll
        for (int k = 0; k < KS; k++) {
            sa[k] = __shfl_sync(0xffffffffu, sa_own, k);
            sx[k] = __shfl_sync(0xffffffffu, sx_own, k);
        }

        // attention: lane o<9 computes logit o, broadcast 1+sigmoid
        float attp = 0.f;
        if (lane < KS) {
            float a = sm_ab[lane];
#pragma unroll
            for (int k = 0; k < KS; k++)
                a += sa[k] * sm_aw[(lane * 2    ) * KS + k]
                   + sx[k] * sm_aw[(lane * 2 + 1) * KS + k];
            attp = 1.0f + 1.0f / (1.0f + __expf(-a));
        }
        float ap[KS];
#pragma unroll
        for (int k = 0; k < KS; k++)
            ap[k] = __shfl_sync(0xffffffffu, attp, k);

        // depthwise accumulate in registers
        float4 acc = db;
#pragma unroll
        for (int k = 0; k < KS; k++) {
            acc.x = fmaf(v[k].x, ap[k] * w0[k], acc.x);
            acc.y = fmaf(v[k].y, ap[k] * w1[k], acc.y);
            acc.z = fmaf(v[k].z, ap[k] * w2[k], acc.z);
            acc.w = fmaf(v[k].w, ap[k] * w3[k], acc.w);
        }
        *(float4*)(sm_out + ll * OSTR + c0) = acc;
    }
    __syncthreads();

    // epilogue: coalesced stores + BN stats
    const int c    = t >> 1;
    const int half = t & 1;
    const int q    = l0 >> 14;                         // l0 / PLANE
    const int rr   = (l0 & (PLANE - 1)) + half * 16;
    float* ob = dout + (size_t)q * (C * PLANE) + (size_t)c * PLANE + rr;

    float s1 = 0.f, s2 = 0.f;
#pragma unroll
    for (int i = 0; i < 4; i++) {
        float4 o4;
        o4.x = sm_out[(half * 16 + i * 4 + 0) * OSTR + c];
        o4.y = sm_out[(half * 16 + i * 4 + 1) * OSTR + c];
        o4.z = sm_out[(half * 16 + i * 4 + 2) * OSTR + c];
        o4.w = sm_out[(half * 16 + i * 4 + 3) * OSTR + c];
        s1 += (o4.x + o4.y) + (o4.z + o4.w);
        s2 += o4.x * o4.x + o4.y * o4.y + o4.z * o4.z + o4.w * o4.w;
        ((float4*)ob)[i] = o4;
    }

    s1 += __shfl_xor_sync(0xffffffffu, s1, 1);
    s2 += __shfl_xor_sync(0xffffffffu, s2, 1);
    if (half == 0) {
        const int bkt = blockIdx.x & (NB - 1);
        atomicAdd(&g_sum[c * NB + bkt],   (double)s1);
        atomicAdd(&g_sumsq[c * NB + bkt], (double)s2);
    }
}

// ---------------------------------------------------------------------------
// 256 threads: pair (c, half) each sums 16 buckets, combine via shfl.
__global__ void bn_params_k(const float* __restrict__ gamma,
                            const float* __restrict__ beta) {
    int t = threadIdx.x;
    int c = t >> 1, half = t & 1;
    double s1 = 0.0, s2 = 0.0;
#pragma unroll
    for (int b = 0; b < NB / 2; b++) {
        int idx = c * NB + half * (NB / 2) + b;
        s1 += g_sum[idx]; s2 += g_sumsq[idx];
    }
    s1 += __shfl_xor_sync(0xffffffffu, s1, 1);
    s2 += __shfl_xor_sync(0xffffffffu, s2, 1);
    if (half == 0) {
        double mean = s1 * (1.0 / LTOT);
        double var  = s2 * (1.0 / LTOT) - mean * mean;
        float inv = rsqrtf((float)var + 1e-5f);
        float a = gamma[c] * inv;
        g_a[c] = a;
        g_b[c] = beta[c] - (float)mean * a;
    }
}

__global__ void finalize_k(float* __restrict__ out) {
    int i = blockIdx.x * blockDim.x + threadIdx.x;    // float4 index
    int c = (i >> 12) & 127;                          // (i*4) / PLANE % C
    float a = g_a[c], b = g_b[c];
    float4 v = ((const float4*)out)[i];
    float4 r;
    r.x = a * v.x + b;  r.x = r.x / (1.f + __expf(-r.x));
    r.y = a * v.y + b;  r.y = r.y / (1.f + __expf(-r.y));
    r.z = a * v.z + b;  r.z = r.z / (1.f + __expf(-r.z));
    r.w = a * v.w + b;  r.w = r.w / (1.f + __expf(-r.w));
    ((float4*)out)[i] = r;
}

// ---------------------------------------------------------------------------
extern "C" void kernel_launch(void* const* d_in, const int* in_sizes, int n_in,
                              void* d_out, int out_size) {
    const float* x       = (const float*)d_in[0];
    const int*   codes   = (const int*)  d_in[1];
    const float* att_w   = (const float*)d_in[2];
    const float* att_b   = (const float*)d_in[3];
    const float* depth_w = (const float*)d_in[4];
    const float* depth_b = (const float*)d_in[5];
    const float* gamma   = (const float*)d_in[6];
    const float* beta    = (const float*)d_in[7];
    float* out = (float*)d_out;

    rowstat_k<<<HW / 256, 256>>>(x);
    transpose_k<<<dim3(HW / 32, C / 32), dim3(32, 8)>>>(x);
    main_k<<<LTOT / TLB, 256>>>(codes, att_w, att_b, depth_w, depth_b, out);
    bn_params_k<<<1, 256>>>(gamma, beta);
    finalize_k<<<(LTOT * C / 4) / 256, 256>>>(out);
}

// round 5
// speedup vs baseline: 1.8906x; 1.0342x over previous
#include <cuda_runtime.h>

#define HW     131072      // h*w = 256*512
#define C      128
#define LTOT   163840      // Q*M*M
#define KS     9
#define TLB    32          // l-values per block
#define WPB    8           // warps per block
#define ROUNDS (TLB/WPB)
#define OSTR   132         // staging stride (words) per l row
#define PLANE  16384       // M*M
#define NB     16          // BN stat buckets

// Scratch (allocation-free rule: device globals)
__device__ __align__(16) float  g_xt[(size_t)HW * C];   // transposed x: [hw][c]
__device__ __align__(8)  float2 g_stat[HW];             // per-position (mean, max) over c
__device__ __align__(16) float  g_wt[KS * C];           // depth_w transposed: [k][c]
__device__ double g_sum[C * NB];
__device__ double g_sumsq[C * NB];
__device__ float  g_a[C];
__device__ float  g_b[C];

// ---------------------------------------------------------------------------
// x [C][HW] -> g_xt [HW][C], fused per-position channel mean/max -> g_stat.
// Block = 32 hw positions x all 128 channels (4 c-tiles of 32).
// Block 0 also zeroes BN buckets and transposes depth_w -> g_wt.
__global__ void __launch_bounds__(256) transpose_k(const float* __restrict__ x,
                                                   const float* __restrict__ depth_w) {
    __shared__ float tile[32][33];
    __shared__ float sms[8][33];
    __shared__ float smm[8][33];
    const int hw0 = blockIdx.x * 32;
    const int tx = threadIdx.x, ty = threadIdx.y;

    if (blockIdx.x == 0) {
        int tid = ty * 32 + tx;
        for (int i = tid; i < C * NB; i += 256) { g_sum[i] = 0.0; g_sumsq[i] = 0.0; }
        for (int i = tid; i < KS * C; i += 256) {
            int k = i / C, c = i % C;
            g_wt[k * C + c] = depth_w[c * KS + k];
        }
    }

    float s = 0.f, m = -3.4e38f;
#pragma unroll
    for (int cy = 0; cy < 4; cy++) {
        const int c0 = cy * 32;
        __syncthreads();
#pragma unroll
        for (int i = 0; i < 32; i += 8) {
            float v = x[(size_t)(c0 + ty + i) * HW + hw0 + tx];
            tile[ty + i][tx] = v;
            s += v;
            m = fmaxf(m, v);
        }
        __syncthreads();
#pragma unroll
        for (int i = 0; i < 32; i += 8)
            g_xt[(size_t)(hw0 + ty + i) * C + c0 + tx] = tile[tx][ty + i];
    }
    sms[ty][tx] = s;
    smm[ty][tx] = m;
    __syncthreads();
    if (ty == 0) {
        float S = 0.f, M = -3.4e38f;
#pragma unroll
        for (int j = 0; j < 8; j++) { S += sms[j][tx]; M = fmaxf(M, smm[j][tx]); }
        g_stat[hw0 + tx] = make_float2(S * (1.0f / C), M);
    }
}

// ---------------------------------------------------------------------------
// One block = 32 l values; 8 warps, each warp one l per round (4 rounds).
// Per warp-round: stat load first (long chain), 9 independent LDG.128 gathers,
// in-warp attention, depthwise accumulate with w from smem (LDS.128 per k),
// STS.128 stage. Epilogue: coalesced float4 stores + bucketed BN atomics.
__global__ void __launch_bounds__(256, 3) main_k(
    const int*   __restrict__ codes,
    const float* __restrict__ att_w,   // [KS][2][KS]
    const float* __restrict__ att_b,   // [KS]
    const float* __restrict__ depth_b, // [C]
    float*       __restrict__ dout)
{
    __shared__ float sm_out[TLB * OSTR];       // [l_local][c] staging
    __shared__ float sm_w[KS * C];             // depth_w [k][c]
    __shared__ float sm_aw[KS * 2 * KS];       // att_w copy
    __shared__ float sm_ab[KS];
    __shared__ int   sidx[TLB * KS];           // 288 codes

    const int t    = threadIdx.x;
    const int lane = t & 31;
    const int wid  = t >> 5;
    const int l0   = blockIdx.x * TLB;
    const int c0   = lane * 4;

    if (t < KS * 2 * KS) sm_aw[t] = att_w[t];
    if (t < KS)          sm_ab[t] = att_b[t];
    for (int i = t; i < TLB * KS; i += 256) sidx[i] = codes[l0 * KS + i];
    for (int i = t; i < KS * C; i += 256)   sm_w[i] = g_wt[i];
    __syncthreads();

#pragma unroll
    for (int r = 0; r < ROUNDS; r++) {
        const int ll = r * WPB + wid;          // local l

        // stats first: start the attention dependency chain early
        float sa_own = 0.f, sx_own = 0.f;
        if (lane < KS) {
            float2 st = g_stat[sidx[ll * KS + lane]];
            sa_own = st.x; sx_own = st.y;
        }

        // gather: 9 independent LDG.128 (indices via LDS broadcast)
        float4 v[KS];
#pragma unroll
        for (int k = 0; k < KS; k++) {
            int j = sidx[ll * KS + k];
            v[k] = *(const float4*)(g_xt + (size_t)j * C + c0);
        }

        float sa[KS], sx[KS];
#pragma unroll
        for (int k = 0; k < KS; k++) {
            sa[k] = __shfl_sync(0xffffffffu, sa_own, k);
            sx[k] = __shfl_sync(0xffffffffu, sx_own, k);
        }

        // attention: lane o<9 computes logit o, broadcast 1+sigmoid
        float attp = 0.f;
        if (lane < KS) {
            float a = sm_ab[lane];
#pragma unroll
            for (int k = 0; k < KS; k++)
                a += sa[k] * sm_aw[(lane * 2    ) * KS + k]
                   + sx[k] * sm_aw[(lane * 2 + 1) * KS + k];
            attp = 1.0f + 1.0f / (1.0f + __expf(-a));
        }
        float ap[KS];
#pragma unroll
        for (int k = 0; k < KS; k++)
            ap[k] = __shfl_sync(0xffffffffu, attp, k);

        // depthwise accumulate, w streamed from smem (conflict-free LDS.128)
        float4 acc = make_float4(0.f, 0.f, 0.f, 0.f);
#pragma unroll
        for (int k = 0; k < KS; k++) {
            float4 w4 = *(const float4*)(sm_w + k * C + c0);
            acc.x = fmaf(v[k].x, ap[k] * w4.x, acc.x);
            acc.y = fmaf(v[k].y, ap[k] * w4.y, acc.y);
            acc.z = fmaf(v[k].z, ap[k] * w4.z, acc.z);
            acc.w = fmaf(v[k].w, ap[k] * w4.w, acc.w);
        }
        *(float4*)(sm_out + ll * OSTR + c0) = acc;
    }
    __syncthreads();

    // epilogue: coalesced stores + BN stats (depth_b folded in here)
    const int c    = t >> 1;
    const int half = t & 1;
    const int q    = l0 >> 14;                         // l0 / PLANE
    const int rr   = (l0 & (PLANE - 1)) + half * 16;
    const float dbc = depth_b[c];
    float* ob = dout + (size_t)q * (C * PLANE) + (size_t)c * PLANE + rr;

    float s1 = 0.f, s2 = 0.f;
#pragma unroll
    for (int i = 0; i < 4; i++) {
        float4 o4;
        o4.x = sm_out[(half * 16 + i * 4 + 0) * OSTR + c] + dbc;
        o4.y = sm_out[(half * 16 + i * 4 + 1) * OSTR + c] + dbc;
        o4.z = sm_out[(half * 16 + i * 4 + 2) * OSTR + c] + dbc;
        o4.w = sm_out[(half * 16 + i * 4 + 3) * OSTR + c] + dbc;
        s1 += (o4.x + o4.y) + (o4.z + o4.w);
        s2 += o4.x * o4.x + o4.y * o4.y + o4.z * o4.z + o4.w * o4.w;
        ((float4*)ob)[i] = o4;
    }

    s1 += __shfl_xor_sync(0xffffffffu, s1, 1);
    s2 += __shfl_xor_sync(0xffffffffu, s2, 1);
    if (half == 0) {
        const int bkt = blockIdx.x & (NB - 1);
        atomicAdd(&g_sum[c * NB + bkt],   (double)s1);
        atomicAdd(&g_sumsq[c * NB + bkt], (double)s2);
    }
}

// ---------------------------------------------------------------------------
// 256 threads: pair (c, half) each sums NB/2 buckets, combine via shfl.
__global__ void bn_params_k(const float* __restrict__ gamma,
                            const float* __restrict__ beta) {
    int t = threadIdx.x;
    int c = t >> 1, half = t & 1;
    double s1 = 0.0, s2 = 0.0;
#pragma unroll
    for (int b = 0; b < NB / 2; b++) {
        int idx = c * NB + half * (NB / 2) + b;
        s1 += g_sum[idx]; s2 += g_sumsq[idx];
    }
    s1 += __shfl_xor_sync(0xffffffffu, s1, 1);
    s2 += __shfl_xor_sync(0xffffffffu, s2, 1);
    if (half == 0) {
        double mean = s1 * (1.0 / LTOT);
        double var  = s2 * (1.0 / LTOT) - mean * mean;
        float inv = rsqrtf((float)var + 1e-5f);
        float a = gamma[c] * inv;
        g_a[c] = a;
        g_b[c] = beta[c] - (float)mean * a;
    }
}

__global__ void finalize_k(float* __restrict__ out) {
    int i = blockIdx.x * blockDim.x + threadIdx.x;    // float4 index
    int c = (i >> 12) & 127;                          // (i*4) / PLANE % C
    float a = g_a[c], b = g_b[c];
    float4 v = ((const float4*)out)[i];
    float4 r;
    r.x = a * v.x + b;  r.x = r.x / (1.f + __expf(-r.x));
    r.y = a * v.y + b;  r.y = r.y / (1.f + __expf(-r.y));
    r.z = a * v.z + b;  r.z = r.z / (1.f + __expf(-r.z));
    r.w = a * v.w + b;  r.w = r.w / (1.f + __expf(-r.w));
    ((float4*)out)[i] = r;
}

// ---------------------------------------------------------------------------
extern "C" void kernel_launch(void* const* d_in, const int* in_sizes, int n_in,
                              void* d_out, int out_size) {
    const float* x       = (const float*)d_in[0];
    const int*   codes   = (const int*)  d_in[1];
    const float* att_w   = (const float*)d_in[2];
    const float* att_b   = (const float*)d_in[3];
    const float* depth_w = (const float*)d_in[4];
    const float* depth_b = (const float*)d_in[5];
    const float* gamma   = (const float*)d_in[6];
    const float* beta    = (const float*)d_in[7];
    float* out = (float*)d_out;

    transpose_k<<<HW / 32, dim3(32, 8)>>>(x, depth_w);
    main_k<<<LTOT / TLB, 256>>>(codes, att_w, att_b, depth_b, out);
    bn_params_k<<<1, 256>>>(gamma, beta);
    finalize_k<<<(LTOT * C / 4) / 256, 256>>>(out);
}

// round 6
// speedup vs baseline: 2.6137x; 1.3825x over previous
#include <cuda_runtime.h>
#include <cuda_fp16.h>

#define HW     131072      // h*w = 256*512
#define C      128
#define LTOT   163840      // Q*M*M
#define KS     9
#define TLB    32          // l-values per block
#define WPB    8           // warps per block
#define ROUNDS (TLB/WPB)
#define OSTR   132         // staging stride (words) per l row
#define PLANE  16384       // M*M
#define NB     16          // BN stat buckets

// Scratch (allocation-free rule: device globals)
__device__ __align__(16) __half g_xh[(size_t)HW * C];   // transposed x (fp16): [hw][c]
__device__ __align__(8)  float2 g_stat[HW];             // per-position (mean, max), fp32
__device__ __align__(16) float  g_wt[KS * C];           // depth_w transposed: [k][c]
__device__ double g_sum[C * NB];
__device__ double g_sumsq[C * NB];
__device__ float  g_a[C];
__device__ float  g_b[C];

// ---------------------------------------------------------------------------
// x [C][HW] -> g_xh [HW][C] (fp16), fused fp32 per-position mean/max -> g_stat.
// One block = 32 hw positions x all 128 channels.
// Block 0 also zeroes BN buckets and transposes depth_w -> g_wt.
__global__ void __launch_bounds__(256) transpose_k(const float* __restrict__ x,
                                                   const float* __restrict__ depth_w) {
    __shared__ float tile[C][33];          // [c][hw_local]
    __shared__ float sms[8][32];
    __shared__ float smm[8][32];
    const int hw0 = blockIdx.x * 32;
    const int t  = threadIdx.x;
    const int tx = t & 31, ty = t >> 5;

    if (blockIdx.x == 0) {
        for (int i = t; i < C * NB; i += 256) { g_sum[i] = 0.0; g_sumsq[i] = 0.0; }
        for (int i = t; i < KS * C; i += 256) {
            int k = i / C, c = i % C;
            g_wt[k * C + c] = depth_w[c * KS + k];
        }
    }

    float s = 0.f, m = -3.4e38f;
#pragma unroll
    for (int i = 0; i < C; i += 8) {
        float v = x[(size_t)(i + ty) * HW + hw0 + tx];
        tile[i + ty][tx] = v;
        s += v;
        m = fmaxf(m, v);
    }
    sms[ty][tx] = s;
    smm[ty][tx] = m;
    __syncthreads();

    // coalesced half2 writes: thread t -> (hw_local = t/64 + 4*i, c_pair = t%64)
    const int hwl = t >> 6;
    const int cp  = t & 63;
#pragma unroll
    for (int i = 0; i < 32; i += 4) {
        const int hw = hwl + i;
        __half2 h = __floats2half2_rn(tile[cp * 2][hw], tile[cp * 2 + 1][hw]);
        *(__half2*)(g_xh + (size_t)(hw0 + hw) * C + cp * 2) = h;
    }
    if (ty == 0) {
        float S = 0.f, M = -3.4e38f;
#pragma unroll
        for (int j = 0; j < 8; j++) { S += sms[j][tx]; M = fmaxf(M, smm[j][tx]); }
        g_stat[hw0 + tx] = make_float2(S * (1.0f / C), M);
    }
}

// ---------------------------------------------------------------------------
// One block = 32 l values; 8 warps, each warp one l per round (4 rounds).
// fp16 gathers (LDG.64/lane), fp32 stats precomputed, in-warp attention,
// depthwise accumulate in fp32, STS.128 stage, streaming output stores.
__global__ void __launch_bounds__(256, 3) main_k(
    const int*   __restrict__ codes,
    const float* __restrict__ att_w,   // [KS][2][KS]
    const float* __restrict__ att_b,   // [KS]
    const float* __restrict__ depth_b, // [C]
    float*       __restrict__ dout)
{
    __shared__ float sm_out[TLB * OSTR];       // [l_local][c] staging
    __shared__ float sm_w[KS * C];             // depth_w [k][c]
    __shared__ float sm_aw[KS * 2 * KS];       // att_w copy
    __shared__ float sm_ab[KS];
    __shared__ int   sidx[TLB * KS];           // 288 codes

    const int t    = threadIdx.x;
    const int lane = t & 31;
    const int wid  = t >> 5;
    const int l0   = blockIdx.x * TLB;
    const int c0   = lane * 4;

    if (t < KS * 2 * KS) sm_aw[t] = att_w[t];
    if (t < KS)          sm_ab[t] = att_b[t];
    for (int i = t; i < TLB * KS; i += 256) sidx[i] = codes[l0 * KS + i];
    for (int i = t; i < KS * C; i += 256)   sm_w[i] = g_wt[i];
    __syncthreads();

#pragma unroll
    for (int r = 0; r < ROUNDS; r++) {
        const int ll = r * WPB + wid;          // local l

        // stats first: start the attention dependency chain early
        float sa_own = 0.f, sx_own = 0.f;
        if (lane < KS) {
            float2 st = g_stat[sidx[ll * KS + lane]];
            sa_own = st.x; sx_own = st.y;
        }

        // gather: 9 independent LDG.64 (4 halfs per lane)
        uint2 v[KS];
#pragma unroll
        for (int k = 0; k < KS; k++) {
            int j = sidx[ll * KS + k];
            v[k] = *(const uint2*)(g_xh + (size_t)j * C + c0);
        }

        float sa[KS], sx[KS];
#pragma unroll
        for (int k = 0; k < KS; k++) {
            sa[k] = __shfl_sync(0xffffffffu, sa_own, k);
            sx[k] = __shfl_sync(0xffffffffu, sx_own, k);
        }

        // attention: lane o<9 computes logit o, broadcast 1+sigmoid
        float attp = 0.f;
        if (lane < KS) {
            float a = sm_ab[lane];
#pragma unroll
            for (int k = 0; k < KS; k++)
                a += sa[k] * sm_aw[(lane * 2    ) * KS + k]
                   + sx[k] * sm_aw[(lane * 2 + 1) * KS + k];
            attp = 1.0f + 1.0f / (1.0f + __expf(-a));
        }
        float ap[KS];
#pragma unroll
        for (int k = 0; k < KS; k++)
            ap[k] = __shfl_sync(0xffffffffu, attp, k);

        // depthwise accumulate in fp32, w streamed from smem (LDS.128)
        float4 acc = make_float4(0.f, 0.f, 0.f, 0.f);
#pragma unroll
        for (int k = 0; k < KS; k++) {
            float4 w4 = *(const float4*)(sm_w + k * C + c0);
            float2 x01 = __half22float2(*(__half2*)&v[k].x);
            float2 x23 = __half22float2(*(__half2*)&v[k].y);
            acc.x = fmaf(x01.x, ap[k] * w4.x, acc.x);
            acc.y = fmaf(x01.y, ap[k] * w4.y, acc.y);
            acc.z = fmaf(x23.x, ap[k] * w4.z, acc.z);
            acc.w = fmaf(x23.y, ap[k] * w4.w, acc.w);
        }
        *(float4*)(sm_out + ll * OSTR + c0) = acc;
    }
    __syncthreads();

    // epilogue: coalesced streaming stores + BN stats (depth_b folded in)
    const int c    = t >> 1;
    const int half = t & 1;
    const int q    = l0 >> 14;                         // l0 / PLANE
    const int rr   = (l0 & (PLANE - 1)) + half * 16;
    const float dbc = depth_b[c];
    float* ob = dout + (size_t)q * (C * PLANE) + (size_t)c * PLANE + rr;

    float s1 = 0.f, s2 = 0.f;
#pragma unroll
    for (int i = 0; i < 4; i++) {
        float4 o4;
        o4.x = sm_out[(half * 16 + i * 4 + 0) * OSTR + c] + dbc;
        o4.y = sm_out[(half * 16 + i * 4 + 1) * OSTR + c] + dbc;
        o4.z = sm_out[(half * 16 + i * 4 + 2) * OSTR + c] + dbc;
        o4.w = sm_out[(half * 16 + i * 4 + 3) * OSTR + c] + dbc;
        s1 += (o4.x + o4.y) + (o4.z + o4.w);
        s2 += o4.x * o4.x + o4.y * o4.y + o4.z * o4.z + o4.w * o4.w;
        __stcs((float4*)ob + i, o4);
    }

    s1 += __shfl_xor_sync(0xffffffffu, s1, 1);
    s2 += __shfl_xor_sync(0xffffffffu, s2, 1);
    if (half == 0) {
        const int bkt = blockIdx.x & (NB - 1);
        atomicAdd(&g_sum[c * NB + bkt],   (double)s1);
        atomicAdd(&g_sumsq[c * NB + bkt], (double)s2);
    }
}

// ---------------------------------------------------------------------------
__global__ void bn_params_k(const float* __restrict__ gamma,
                            const float* __restrict__ beta) {
    int t = threadIdx.x;
    int c = t >> 1, half = t & 1;
    double s1 = 0.0, s2 = 0.0;
#pragma unroll
    for (int b = 0; b < NB / 2; b++) {
        int idx = c * NB + half * (NB / 2) + b;
        s1 += g_sum[idx]; s2 += g_sumsq[idx];
    }
    s1 += __shfl_xor_sync(0xffffffffu, s1, 1);
    s2 += __shfl_xor_sync(0xffffffffu, s2, 1);
    if (half == 0) {
        double mean = s1 * (1.0 / LTOT);
        double var  = s2 * (1.0 / LTOT) - mean * mean;
        float inv = rsqrtf((float)var + 1e-5f);
        float a = gamma[c] * inv;
        g_a[c] = a;
        g_b[c] = beta[c] - (float)mean * a;
    }
}

__global__ void finalize_k(float* __restrict__ out) {
    int i = blockIdx.x * blockDim.x + threadIdx.x;    // float4 index
    int c = (i >> 12) & 127;                          // (i*4) / PLANE % C
    float a = g_a[c], b = g_b[c];
    float4 v = __ldcs((const float4*)out + i);
    float4 r;
    r.x = a * v.x + b;  r.x = r.x / (1.f + __expf(-r.x));
    r.y = a * v.y + b;  r.y = r.y / (1.f + __expf(-r.y));
    r.z = a * v.z + b;  r.z = r.z / (1.f + __expf(-r.z));
    r.w = a * v.w + b;  r.w = r.w / (1.f + __expf(-r.w));
    __stcs((float4*)out + i, r);
}

// ---------------------------------------------------------------------------
extern "C" void kernel_launch(void* const* d_in, const int* in_sizes, int n_in,
                              void* d_out, int out_size) {
    const float* x       = (const float*)d_in[0];
    const int*   codes   = (const int*)  d_in[1];
    const float* att_w   = (const float*)d_in[2];
    const float* att_b   = (const float*)d_in[3];
    const float* depth_w = (const float*)d_in[4];
    const float* depth_b = (const float*)d_in[5];
    const float* gamma   = (const float*)d_in[6];
    const float* beta    = (const float*)d_in[7];
    float* out = (float*)d_out;

    transpose_k<<<HW / 32, 256>>>(x, depth_w);
    main_k<<<LTOT / TLB, 256>>>(codes, att_w, att_b, depth_b, out);
    bn_params_k<<<1, 256>>>(gamma, beta);
    finalize_k<<<(LTOT * C / 4) / 256, 256>>>(out);
}

// round 7
// speedup vs baseline: 2.6900x; 1.0292x over previous
#include <cuda_runtime.h>
#include <cuda_fp16.h>

#define HW     131072      // h*w = 256*512
#define C      128
#define LTOT   163840      // Q*M*M
#define KS     9
#define TLB    32          // l-values per block
#define WPB    8           // warps per block
#define ROUNDS (TLB/WPB)
#define NTASK  (TLB*KS)    // 288 (l,k)/(l,o) tasks per block
#define OSTR   132         // staging stride (words) per l row
#define PLANE  16384       // M*M
#define NB     16          // BN stat buckets
#define NBLK   (LTOT/TLB)  // 5120 main blocks

// Scratch (allocation-free rule: device globals)
__device__ __align__(16) __half g_xh[(size_t)HW * C];   // transposed x (fp16): [hw][c]
__device__ __align__(8)  float2 g_stat[HW];             // per-position (mean, max), fp32
__device__ __align__(16) float  g_wt[KS * C];           // depth_w transposed: [k][c]
__device__ double g_sum[C * NB];
__device__ double g_sumsq[C * NB];
__device__ float  g_a[C];
__device__ float  g_b[C];
__device__ unsigned g_done;

// ---------------------------------------------------------------------------
// x [C][HW] -> g_xh [HW][C] (fp16), fused fp32 per-position mean/max -> g_stat.
// Block 0 also zeroes BN buckets / completion flag and transposes depth_w.
__global__ void __launch_bounds__(256) transpose_k(const float* __restrict__ x,
                                                   const float* __restrict__ depth_w) {
    __shared__ float tile[C][33];          // [c][hw_local]
    __shared__ float sms[8][32];
    __shared__ float smm[8][32];
    const int hw0 = blockIdx.x * 32;
    const int t  = threadIdx.x;
    const int tx = t & 31, ty = t >> 5;

    if (blockIdx.x == 0) {
        if (t == 0) g_done = 0;
        for (int i = t; i < C * NB; i += 256) { g_sum[i] = 0.0; g_sumsq[i] = 0.0; }
        for (int i = t; i < KS * C; i += 256) {
            int k = i / C, c = i % C;
            g_wt[k * C + c] = depth_w[c * KS + k];
        }
    }

    float s = 0.f, m = -3.4e38f;
#pragma unroll
    for (int i = 0; i < C; i += 8) {
        float v = x[(size_t)(i + ty) * HW + hw0 + tx];
        tile[i + ty][tx] = v;
        s += v;
        m = fmaxf(m, v);
    }
    sms[ty][tx] = s;
    smm[ty][tx] = m;
    __syncthreads();

    const int hwl = t >> 6;
    const int cp  = t & 63;
#pragma unroll
    for (int i = 0; i < 32; i += 4) {
        const int hw = hwl + i;
        __half2 h = __floats2half2_rn(tile[cp * 2][hw], tile[cp * 2 + 1][hw]);
        *(__half2*)(g_xh + (size_t)(hw0 + hw) * C + cp * 2) = h;
    }
    if (ty == 0) {
        float S = 0.f, M = -3.4e38f;
#pragma unroll
        for (int j = 0; j < 8; j++) { S += sms[j][tx]; M = fmaxf(M, smm[j][tx]); }
        g_stat[hw0 + tx] = make_float2(S * (1.0f / C), M);
    }
}

// ---------------------------------------------------------------------------
// One block = 32 l values.
// Phase 1 (thread-parallel): codes + per-position stats -> smem.
// Phase 2 (thread-parallel): 288 attention logits + sigmoid -> smem.
// Phase 3 (warp-parallel, 4 rounds): 9 fp16 gathers + depthwise -> staging.
// Epilogue: coalesced streaming stores + bucketed BN atomics; LAST block
// computes the BN normalization params (fused bn_params).
__global__ void __launch_bounds__(256, 4) main_k(
    const int*   __restrict__ codes,
    const float* __restrict__ att_w,   // [KS][2][KS]
    const float* __restrict__ att_b,   // [KS]
    const float* __restrict__ depth_b, // [C]
    const float* __restrict__ gamma,
    const float* __restrict__ beta,
    float*       __restrict__ dout)
{
    __shared__ float  sm_out[TLB * OSTR];   // [l_local][c] staging
    __shared__ float  sm_w[KS * C];         // depth_w [k][c]
    __shared__ float2 sast[NTASK];          // (avg,max) per (l,k)
    __shared__ float  sm_attp[NTASK];       // 1+sigmoid per (l,o)
    __shared__ float  sm_aw[KS * 2 * KS];
    __shared__ float  sm_ab[KS];
    __shared__ int    sidx[NTASK];
    __shared__ unsigned s_rank;

    const int t    = threadIdx.x;
    const int lane = t & 31;
    const int wid  = t >> 5;
    const int l0   = blockIdx.x * TLB;
    const int c0   = lane * 4;

    if (t < KS * 2 * KS) sm_aw[t] = att_w[t];
    if (t < KS)          sm_ab[t] = att_b[t];
    for (int i = t; i < KS * C; i += 256) sm_w[i] = g_wt[i];

    // phase 1: codes + stats
    for (int i = t; i < NTASK; i += 256) {
        int j = codes[l0 * KS + i];
        sidx[i] = j;
        sast[i] = g_stat[j];
    }
    __syncthreads();

    // phase 2: attention logits (one thread per (l,o))
    for (int i = t; i < NTASK; i += 256) {
        const int l = i / KS, o = i % KS;
        float a = sm_ab[o];
#pragma unroll
        for (int k = 0; k < KS; k++) {
            float2 st = sast[l * KS + k];
            a += st.x * sm_aw[(o * 2    ) * KS + k]
               + st.y * sm_aw[(o * 2 + 1) * KS + k];
        }
        sm_attp[i] = 1.0f + 1.0f / (1.0f + __expf(-a));
    }
    __syncthreads();

    // phase 3: gathers + depthwise
#pragma unroll
    for (int r = 0; r < ROUNDS; r++) {
        const int ll = r * WPB + wid;

        uint2 v[KS];
#pragma unroll
        for (int k = 0; k < KS; k++) {
            int j = sidx[ll * KS + k];
            v[k] = *(const uint2*)(g_xh + (size_t)j * C + c0);
        }

        float4 acc = make_float4(0.f, 0.f, 0.f, 0.f);
#pragma unroll
        for (int k = 0; k < KS; k++) {
            const float apk = sm_attp[ll * KS + k];     // broadcast LDS
            float4 w4 = *(const float4*)(sm_w + k * C + c0);
            float2 x01 = __half22float2(*(__half2*)&v[k].x);
            float2 x23 = __half22float2(*(__half2*)&v[k].y);
            acc.x = fmaf(x01.x, apk * w4.x, acc.x);
            acc.y = fmaf(x01.y, apk * w4.y, acc.y);
            acc.z = fmaf(x23.x, apk * w4.z, acc.z);
            acc.w = fmaf(x23.y, apk * w4.w, acc.w);
        }
        *(float4*)(sm_out + ll * OSTR + c0) = acc;
    }
    __syncthreads();

    // epilogue: coalesced streaming stores + BN stats (depth_b folded in)
    const int c    = t >> 1;
    const int half = t & 1;
    const int q    = l0 >> 14;
    const int rr   = (l0 & (PLANE - 1)) + half * 16;
    const float dbc = depth_b[c];
    float* ob = dout + (size_t)q * (C * PLANE) + (size_t)c * PLANE + rr;

    float s1 = 0.f, s2 = 0.f;
#pragma unroll
    for (int i = 0; i < 4; i++) {
        float4 o4;
        o4.x = sm_out[(half * 16 + i * 4 + 0) * OSTR + c] + dbc;
        o4.y = sm_out[(half * 16 + i * 4 + 1) * OSTR + c] + dbc;
        o4.z = sm_out[(half * 16 + i * 4 + 2) * OSTR + c] + dbc;
        o4.w = sm_out[(half * 16 + i * 4 + 3) * OSTR + c] + dbc;
        s1 += (o4.x + o4.y) + (o4.z + o4.w);
        s2 += o4.x * o4.x + o4.y * o4.y + o4.z * o4.z + o4.w * o4.w;
        __stcs((float4*)ob + i, o4);
    }

    s1 += __shfl_xor_sync(0xffffffffu, s1, 1);
    s2 += __shfl_xor_sync(0xffffffffu, s2, 1);
    if (half == 0) {
        const int bkt = blockIdx.x & (NB - 1);
        atomicAdd(&g_sum[c * NB + bkt],   (double)s1);
        atomicAdd(&g_sumsq[c * NB + bkt], (double)s2);
    }

    // fused bn_params: last block to finish computes normalization coeffs
    __threadfence();
    __syncthreads();
    if (t == 0) s_rank = atomicAdd(&g_done, 1u);
    __syncthreads();
    if (s_rank == NBLK - 1) {
        __threadfence();
        double s1d = 0.0, s2d = 0.0;
#pragma unroll
        for (int b = 0; b < NB / 2; b++) {
            int idx = c * NB + half * (NB / 2) + b;
            s1d += g_sum[idx]; s2d += g_sumsq[idx];
        }
        s1d += __shfl_xor_sync(0xffffffffu, s1d, 1);
        s2d += __shfl_xor_sync(0xffffffffu, s2d, 1);
        if (half == 0) {
            double mean = s1d * (1.0 / LTOT);
            double var  = s2d * (1.0 / LTOT) - mean * mean;
            float inv = rsqrtf((float)var + 1e-5f);
            float a = gamma[c] * inv;
            g_a[c] = a;
            g_b[c] = beta[c] - (float)mean * a;
        }
    }
}

// ---------------------------------------------------------------------------
__global__ void finalize_k(float* __restrict__ out) {
    int i = blockIdx.x * blockDim.x + threadIdx.x;    // float4 index
    int c = (i >> 12) & 127;                          // (i*4) / PLANE % C
    float a = g_a[c], b = g_b[c];
    float4 v = __ldcs((const float4*)out + i);
    float4 r;
    r.x = a * v.x + b;  r.x = r.x / (1.f + __expf(-r.x));
    r.y = a * v.y + b;  r.y = r.y / (1.f + __expf(-r.y));
    r.z = a * v.z + b;  r.z = r.z / (1.f + __expf(-r.z));
    r.w = a * v.w + b;  r.w = r.w / (1.f + __expf(-r.w));
    __stcs((float4*)out + i, r);
}

// ---------------------------------------------------------------------------
extern "C" void kernel_launch(void* const* d_in, const int* in_sizes, int n_in,
                              void* d_out, int out_size) {
    const float* x       = (const float*)d_in[0];
    const int*   codes   = (const int*)  d_in[1];
    const float* att_w   = (const float*)d_in[2];
    const float* att_b   = (const float*)d_in[3];
    const float* depth_w = (const float*)d_in[4];
    const float* depth_b = (const float*)d_in[5];
    const float* gamma   = (const float*)d_in[6];
    const float* beta    = (const float*)d_in[7];
    float* out = (float*)d_out;

    transpose_k<<<HW / 32, 256>>>(x, depth_w);
    main_k<<<NBLK, 256>>>(codes, att_w, att_b, depth_b, gamma, beta, out);
    finalize_k<<<(LTOT * C / 4) / 256, 256>>>(out);
}

// round 8
// speedup vs baseline: 3.3199x; 1.2342x over previous
#include <cuda_runtime.h>
#include <cuda_fp16.h>

#define HW     131072      // h*w = 256*512
#define C      128
#define LTOT   163840      // Q*M*M
#define KS     9
#define TLB    32          // l-values per block
#define WPB    8           // warps per block
#define ROUNDS (TLB/WPB)
#define NTASK  (TLB*KS)    // 288 (l,k)/(l,o) tasks per block
#define OSTR   132         // staging stride (words) per l row
#define PLANE  16384       // M*M
#define NB     16          // BN stat buckets
#define NBLK   (LTOT/TLB)  // 5120 main blocks

// Scratch (allocation-free rule: device globals)
__device__ __align__(16) __half g_xh[(size_t)HW * C];     // transposed x (fp16): [hw][c]
__device__ __align__(16) __half g_oh[(size_t)LTOT * C];   // pre-BN output (fp16)
__device__ __align__(8)  float2 g_stat[HW];               // per-position (mean, max), fp32
__device__ __align__(16) float  g_wt[KS * C];             // depth_w transposed: [k][c]
__device__ float g_sumf[C * NB];
__device__ float g_sumsqf[C * NB];
__device__ float g_a[C];
__device__ float g_b[C];

// ---------------------------------------------------------------------------
// x [C][HW] -> g_xh [HW][C] (fp16), fused fp32 per-position mean/max -> g_stat.
// x read with streaming hint (keep L2 for g_xh). Block 0 zeroes BN buckets
// and transposes depth_w -> g_wt.
__global__ void __launch_bounds__(256) transpose_k(const float* __restrict__ x,
                                                   const float* __restrict__ depth_w) {
    __shared__ float tile[C][33];          // [c][hw_local]
    __shared__ float sms[8][32];
    __shared__ float smm[8][32];
    const int hw0 = blockIdx.x * 32;
    const int t  = threadIdx.x;
    const int tx = t & 31, ty = t >> 5;

    if (blockIdx.x == 0) {
        for (int i = t; i < C * NB; i += 256) { g_sumf[i] = 0.f; g_sumsqf[i] = 0.f; }
        for (int i = t; i < KS * C; i += 256) {
            int k = i / C, c = i % C;
            g_wt[k * C + c] = depth_w[c * KS + k];
        }
    }

    float s = 0.f, m = -3.4e38f;
#pragma unroll
    for (int i = 0; i < C; i += 8) {
        float v = __ldcs(x + (size_t)(i + ty) * HW + hw0 + tx);
        tile[i + ty][tx] = v;
        s += v;
        m = fmaxf(m, v);
    }
    sms[ty][tx] = s;
    smm[ty][tx] = m;
    __syncthreads();

    const int hwl = t >> 6;
    const int cp  = t & 63;
#pragma unroll
    for (int i = 0; i < 32; i += 4) {
        const int hw = hwl + i;
        __half2 h = __floats2half2_rn(tile[cp * 2][hw], tile[cp * 2 + 1][hw]);
        *(__half2*)(g_xh + (size_t)(hw0 + hw) * C + cp * 2) = h;
    }
    if (ty == 0) {
        float S = 0.f, M = -3.4e38f;
#pragma unroll
        for (int j = 0; j < 8; j++) { S += sms[j][tx]; M = fmaxf(M, smm[j][tx]); }
        g_stat[hw0 + tx] = make_float2(S * (1.0f / C), M);
    }
}

// ---------------------------------------------------------------------------
// One block = 32 l values.
// Phase 1: codes + per-position stats -> smem (thread-parallel).
// Phase 2: 288 attention logits + sigmoid -> smem (thread-parallel).
// Phase 3: software-pipelined fp16 gathers (double-buffered) + depthwise.
// Epilogue: coalesced fp16 stores to scratch + float BN-stat atomics.
__global__ void __launch_bounds__(256, 3) main_k(
    const int*   __restrict__ codes,
    const float* __restrict__ att_w,   // [KS][2][KS]
    const float* __restrict__ att_b,   // [KS]
    const float* __restrict__ depth_b) // [C]
{
    __shared__ float  sm_out[TLB * OSTR];   // [l_local][c] staging
    __shared__ float  sm_w[KS * C];         // depth_w [k][c]
    __shared__ float2 sast[NTASK];          // (avg,max) per (l,k)
    __shared__ float  sm_attp[NTASK];       // 1+sigmoid per (l,o)
    __shared__ float  sm_aw[KS * 2 * KS];
    __shared__ float  sm_ab[KS];
    __shared__ int    sidx[NTASK];

    const int t    = threadIdx.x;
    const int lane = t & 31;
    const int wid  = t >> 5;
    const int l0   = blockIdx.x * TLB;
    const int c0   = lane * 4;

    if (t < KS * 2 * KS) sm_aw[t] = att_w[t];
    if (t < KS)          sm_ab[t] = att_b[t];
    for (int i = t; i < KS * C; i += 256) sm_w[i] = g_wt[i];

    // phase 1: codes + stats
    for (int i = t; i < NTASK; i += 256) {
        int j = __ldg(codes + l0 * KS + i);
        sidx[i] = j;
        sast[i] = g_stat[j];
    }
    __syncthreads();

    // phase 2: attention logits (one thread per (l,o))
    for (int i = t; i < NTASK; i += 256) {
        const int l = i / KS, o = i % KS;
        float a = sm_ab[o];
#pragma unroll
        for (int k = 0; k < KS; k++) {
            float2 st = sast[l * KS + k];
            a += st.x * sm_aw[(o * 2    ) * KS + k]
               + st.y * sm_aw[(o * 2 + 1) * KS + k];
        }
        sm_attp[i] = 1.0f + 1.0f / (1.0f + __expf(-a));
    }
    __syncthreads();

    // phase 3: double-buffered gathers + depthwise
    uint2 vcur[KS], vnxt[KS];
#pragma unroll
    for (int k = 0; k < KS; k++) {
        int j = sidx[wid * KS + k];
        vcur[k] = *(const uint2*)(g_xh + (size_t)j * C + c0);
    }

#pragma unroll
    for (int r = 0; r < ROUNDS; r++) {
        const int ll = r * WPB + wid;

        if (r + 1 < ROUNDS) {
            const int lln = ll + WPB;
#pragma unroll
            for (int k = 0; k < KS; k++) {
                int j = sidx[lln * KS + k];
                vnxt[k] = *(const uint2*)(g_xh + (size_t)j * C + c0);
            }
        }

        float4 acc = make_float4(0.f, 0.f, 0.f, 0.f);
#pragma unroll
        for (int k = 0; k < KS; k++) {
            const float apk = sm_attp[ll * KS + k];     // broadcast LDS
            float4 w4 = *(const float4*)(sm_w + k * C + c0);
            float2 x01 = __half22float2(*(__half2*)&vcur[k].x);
            float2 x23 = __half22float2(*(__half2*)&vcur[k].y);
            acc.x = fmaf(x01.x, apk * w4.x, acc.x);
            acc.y = fmaf(x01.y, apk * w4.y, acc.y);
            acc.z = fmaf(x23.x, apk * w4.z, acc.z);
            acc.w = fmaf(x23.y, apk * w4.w, acc.w);
        }
        *(float4*)(sm_out + ll * OSTR + c0) = acc;

#pragma unroll
        for (int k = 0; k < KS; k++) vcur[k] = vnxt[k];
    }
    __syncthreads();

    // epilogue: fp16 stores to scratch + float BN-stat atomics
    const int c    = t >> 1;
    const int half = t & 1;
    const int q    = l0 >> 14;
    const int rr   = (l0 & (PLANE - 1)) + half * 16;
    const float dbc = depth_b[c];
    __half* ob = g_oh + (size_t)q * (C * PLANE) + (size_t)c * PLANE + rr;

    float s1 = 0.f, s2 = 0.f;
#pragma unroll
    for (int i = 0; i < 4; i++) {
        float4 o4;
        o4.x = sm_out[(half * 16 + i * 4 + 0) * OSTR + c] + dbc;
        o4.y = sm_out[(half * 16 + i * 4 + 1) * OSTR + c] + dbc;
        o4.z = sm_out[(half * 16 + i * 4 + 2) * OSTR + c] + dbc;
        o4.w = sm_out[(half * 16 + i * 4 + 3) * OSTR + c] + dbc;
        s1 += (o4.x + o4.y) + (o4.z + o4.w);
        s2 += o4.x * o4.x + o4.y * o4.y + o4.z * o4.z + o4.w * o4.w;
        __half2 h01 = __floats2half2_rn(o4.x, o4.y);
        __half2 h23 = __floats2half2_rn(o4.z, o4.w);
        uint2 hv = make_uint2(*(unsigned*)&h01, *(unsigned*)&h23);
        *(uint2*)(ob + i * 4) = hv;
    }

    s1 += __shfl_xor_sync(0xffffffffu, s1, 1);
    s2 += __shfl_xor_sync(0xffffffffu, s2, 1);
    if (half == 0) {
        const int bkt = blockIdx.x & (NB - 1);
        atomicAdd(&g_sumf[c * NB + bkt],   s1);
        atomicAdd(&g_sumsqf[c * NB + bkt], s2);
    }
}

// ---------------------------------------------------------------------------
__global__ void bn_params_k(const float* __restrict__ gamma,
                            const float* __restrict__ beta) {
    int t = threadIdx.x;
    int c = t >> 1, half = t & 1;
    double s1 = 0.0, s2 = 0.0;
#pragma unroll
    for (int b = 0; b < NB / 2; b++) {
        int idx = c * NB + half * (NB / 2) + b;
        s1 += (double)g_sumf[idx]; s2 += (double)g_sumsqf[idx];
    }
    s1 += __shfl_xor_sync(0xffffffffu, s1, 1);
    s2 += __shfl_xor_sync(0xffffffffu, s2, 1);
    if (half == 0) {
        double mean = s1 * (1.0 / LTOT);
        double var  = s2 * (1.0 / LTOT) - mean * mean;
        float inv = rsqrtf((float)var + 1e-5f);
        float a = gamma[c] * inv;
        g_a[c] = a;
        g_b[c] = beta[c] - (float)mean * a;
    }
}

// ---------------------------------------------------------------------------
// Reads fp16 scratch (L2-resident), applies BN affine + SiLU, writes fp32 out.
// One thread = 8 halves (16B in, 32B out).
__global__ void finalize_k(float* __restrict__ out) {
    const int i = blockIdx.x * blockDim.x + threadIdx.x;   // 8-half chunk index
    const size_t base = (size_t)i * 8;
    const int c = (int)((base >> 14) & 127);               // (base/PLANE)%C
    const float a = g_a[c], b = g_b[c];

    uint4 h = *((const uint4*)g_oh + i);
    float2 p0 = __half22float2(*(__half2*)&h.x);
    float2 p1 = __half22float2(*(__half2*)&h.y);
    float2 p2 = __half22float2(*(__half2*)&h.z);
    float2 p3 = __half22float2(*(__half2*)&h.w);

    float4 r0, r1;
    r0.x = a * p0.x + b;  r0.x = r0.x / (1.f + __expf(-r0.x));
    r0.y = a * p0.y + b;  r0.y = r0.y / (1.f + __expf(-r0.y));
    r0.z = a * p1.x + b;  r0.z = r0.z / (1.f + __expf(-r0.z));
    r0.w = a * p1.y + b;  r0.w = r0.w / (1.f + __expf(-r0.w));
    r1.x = a * p2.x + b;  r1.x = r1.x / (1.f + __expf(-r1.x));
    r1.y = a * p2.y + b;  r1.y = r1.y / (1.f + __expf(-r1.y));
    r1.z = a * p3.x + b;  r1.z = r1.z / (1.f + __expf(-r1.z));
    r1.w = a * p3.y + b;  r1.w = r1.w / (1.f + __expf(-r1.w));

    __stcs((float4*)out + i * 2,     r0);
    __stcs((float4*)out + i * 2 + 1, r1);
}

// ---------------------------------------------------------------------------
extern "C" void kernel_launch(void* const* d_in, const int* in_sizes, int n_in,
                              void* d_out, int out_size) {
    const float* x       = (const float*)d_in[0];
    const int*   codes   = (const int*)  d_in[1];
    const float* att_w   = (const float*)d_in[2];
    const float* att_b   = (const float*)d_in[3];
    const float* depth_w = (const float*)d_in[4];
    const float* depth_b = (const float*)d_in[5];
    const float* gamma   = (const float*)d_in[6];
    const float* beta    = (const float*)d_in[7];
    float* out = (float*)d_out;

    transpose_k<<<HW / 32, 256>>>(x, depth_w);
    main_k<<<NBLK, 256>>>(codes, att_w, att_b, depth_b);
    bn_params_k<<<1, 256>>>(gamma, beta);
    finalize_k<<<(LTOT * C / 8) / 256, 256>>>(out);
}